// round 10
// baseline (speedup 1.0000x reference)
#include <cuda_runtime.h>
#include <cstdint>

#define SEQ   2048
#define DH    128
#define BQ    256
#define BK    64
#define NBH   64
#define NKT   (SEQ / BK)     // 32
#define KP    136            // K smem row stride (floats)
#define VP    72             // V^T smem row stride (floats)
#define PP    72             // P smem row stride (floats)
#define KBUF  (64 * KP)      // 8704 floats
#define VBUF  (128 * VP)     // 9216 floats
#define KS_OFF 0
#define VS_OFF (2 * KBUF)                 // 17408
#define PS_OFF (VS_OFF + 2 * VBUF)        // 35840
#define SMEM_FLOATS (PS_OFF + 8 * 32 * PP)  // 54272
#define SMEM_BYTES (SMEM_FLOATS * 4)        // 217088 B

__device__ float g_Qp[(size_t)NBH * SEQ * DH];   // tf32, pre-scaled, dim-pair-permuted
__device__ float g_Kp[(size_t)NBH * SEQ * DH];   // tf32, dim-pair-permuted
__device__ float g_Vt[(size_t)NBH * DH * SEQ];   // tf32, transposed [dim][key], key-pair-permuted

__device__ __forceinline__ float tf32r(float x) {
    uint32_t u; asm("cvt.rna.tf32.f32 %0, %1;" : "=r"(u) : "f"(x));
    return __uint_as_float(u);
}
__device__ __forceinline__ uint32_t smem_u32(const void* p) {
    uint32_t a;
    asm("{ .reg .u64 t; cvta.to.shared.u64 t, %1; cvt.u32.u64 %0, t; }" : "=r"(a) : "l"(p));
    return a;
}
__device__ __forceinline__ void cp16(uint32_t dst, const void* src) {
    asm volatile("cp.async.cg.shared.global [%0], [%1], 16;" :: "r"(dst), "l"(src) : "memory");
}
#define CP_COMMIT() asm volatile("cp.async.commit_group;" ::: "memory")
#define CP_WAIT1()  asm volatile("cp.async.wait_group 1;" ::: "memory")

__device__ __forceinline__ void mma_tf32(float c[4],
                                         float a0, float a1, float a2, float a3,
                                         float b0, float b1) {
    asm volatile(
        "mma.sync.aligned.m16n8k8.row.col.f32.tf32.tf32.f32 "
        "{%0,%1,%2,%3}, {%4,%5,%6,%7}, {%8,%9}, {%0,%1,%2,%3};"
        : "+f"(c[0]), "+f"(c[1]), "+f"(c[2]), "+f"(c[3])
        : "r"(__float_as_uint(a0)), "r"(__float_as_uint(a1)),
          "r"(__float_as_uint(a2)), "r"(__float_as_uint(a3)),
          "r"(__float_as_uint(b0)), "r"(__float_as_uint(b1)));
}

// Q/K prep: tf32 round (Q also scaled), permute dims within 8-groups: c -> (c&3)*2 + (c>>2)
__global__ void prep_qk(const float* __restrict__ q, const float* __restrict__ k) {
    const float sc = 0.08838834764831845f;   // 1/sqrt(128)
    size_t i = (size_t)blockIdx.x * blockDim.x + threadIdx.x;
    size_t i4 = i * 4;
    float4 a = ((const float4*)q)[i];
    float4 b = ((const float4*)k)[i];
    float qa[4] = {tf32r(a.x * sc), tf32r(a.y * sc), tf32r(a.z * sc), tf32r(a.w * sc)};
    float kb[4] = {tf32r(b.x), tf32r(b.y), tf32r(b.z), tf32r(b.w)};
    size_t gbase = i4 & ~(size_t)7;
    int within = (int)(i4 & 7);   // 0 or 4
#pragma unroll
    for (int j = 0; j < 4; j++) {
        int c = within + j;
        int pos = (c & 3) * 2 + (c >> 2);
        g_Qp[gbase + pos] = qa[j];
        g_Kp[gbase + pos] = kb[j];
    }
}

// V prep: tf32 round, transpose to [bh][dim][key], permute keys within 8-groups
__global__ void prep_v(const float* __restrict__ v) {
    __shared__ float t[32][33];
    int k0 = blockIdx.x * 32, d0 = blockIdx.y * 32, bh = blockIdx.z;
    int tx = threadIdx.x, ty = threadIdx.y;
    t[ty][tx] = tf32r(v[(size_t)bh * SEQ * DH + (size_t)(k0 + ty) * DH + d0 + tx]);
    __syncthreads();
    int kk = tx;
    int kperm = (kk & ~7) + ((kk & 3) * 2 + ((kk & 7) >> 2));
    g_Vt[(size_t)bh * DH * SEQ + (size_t)(d0 + ty) * SEQ + k0 + kperm] = t[tx][ty];
}

__device__ __forceinline__ void load_K(uint32_t sb, int tid, size_t base, int kt, int buf) {
    const float* kg = g_Kp + base + (size_t)kt * BK * DH;
#pragma unroll
    for (int it = 0; it < 8; it++) {
        int idx = tid + it * 256;        // 64 rows x 32 chunks
        int n = idx >> 5, c = idx & 31;
        cp16(sb + (uint32_t)(KS_OFF + buf * KBUF + n * KP + 4 * c) * 4u,
             kg + (size_t)n * DH + 4 * c);
    }
}
__device__ __forceinline__ void load_V(uint32_t sb, int tid, int bh, int kt, int buf) {
    const float* vg = g_Vt + (size_t)bh * DH * SEQ + kt * BK;
#pragma unroll
    for (int it = 0; it < 8; it++) {
        int idx = tid + it * 256;        // 128 rows x 16 chunks
        int n = idx >> 4, c = idx & 15;
        cp16(sb + (uint32_t)(VS_OFF + buf * VBUF + n * VP + 4 * c) * 4u,
             vg + (size_t)n * SEQ + 4 * c);
    }
}

__global__ void __launch_bounds__(256, 1)
fa_tf32_kernel(const float* __restrict__ mask, float* __restrict__ out) {
    extern __shared__ float smem[];
    const uint32_t sb = smem_u32(smem);

    const int tid  = threadIdx.x;
    const int w    = tid >> 5;
    const int lane = tid & 31;
    const int g    = lane >> 2;
    const int tg   = lane & 3;

    const int qt = blockIdx.x;
    const int bh = blockIdx.y;
    const int q0 = qt * BQ;
    const size_t base = (size_t)bh * SEQ * DH;

    // P store positions under the pair permutation (cols 2tg, 2tg+1)
    const int pp0 = ((2 * tg) & 3) * 2 + ((2 * tg) >> 2);
    const int pp1 = ((2 * tg + 1) & 3) * 2 + ((2 * tg + 1) >> 2);

    float* Ps = smem + PS_OFF + w * (32 * PP);

    // Q row pointers (permuted gmem layout; re-read per iter from L2)
    const float* qr0 = g_Qp + base + (size_t)(q0 + w * 32 + g) * DH;   // block0 row g
    const float* qr1 = qr0 + 8 * DH;                                    // block0 row g+8
    const float* qr2 = qr0 + 16 * DH;                                   // block1 row g
    const float* qr3 = qr0 + 24 * DH;                                   // block1 row g+8

    const float* mrow0 = mask + (size_t)(q0 + w * 32 + g)      * SEQ;
    const float* mrow1 = mask + (size_t)(q0 + w * 32 + g + 8)  * SEQ;
    const float* mrow2 = mask + (size_t)(q0 + w * 32 + g + 16) * SEQ;
    const float* mrow3 = mask + (size_t)(q0 + w * 32 + g + 24) * SEQ;

    float oacc0[16][4], oacc1[16][4];
#pragma unroll
    for (int d = 0; d < 16; d++) {
        oacc0[d][0] = 0.f; oacc0[d][1] = 0.f; oacc0[d][2] = 0.f; oacc0[d][3] = 0.f;
        oacc1[d][0] = 0.f; oacc1[d][1] = 0.f; oacc1[d][2] = 0.f; oacc1[d][3] = 0.f;
    }
    float l00 = 0.f, l01 = 0.f, l10 = 0.f, l11 = 0.f;

    load_K(sb, tid, base, 0, 0);
    load_V(sb, tid, bh, 0, 0);
    CP_COMMIT();

    for (int kt = 0; kt < NKT; kt++) {
        const int cur = kt & 1, nxt = cur ^ 1;
        __syncthreads();
        if (kt + 1 < NKT) { load_K(sb, tid, base, kt + 1, nxt); load_V(sb, tid, bh, kt + 1, nxt); }
        CP_COMMIT();
        CP_WAIT1();
        __syncthreads();

        const float* Ks = smem + KS_OFF + cur * KBUF;
        const float* Vs = smem + VS_OFF + cur * VBUF;

        // ---- S = Q K^T for both 16-row blocks, sharing K B-fragments ----
        float sacc0[8][4], sacc1[8][4];
#pragma unroll
        for (int nb = 0; nb < 8; nb++) {
            sacc0[nb][0] = 0.f; sacc0[nb][1] = 0.f; sacc0[nb][2] = 0.f; sacc0[nb][3] = 0.f;
            sacc1[nb][0] = 0.f; sacc1[nb][1] = 0.f; sacc1[nb][2] = 0.f; sacc1[nb][3] = 0.f;
        }
#pragma unroll 4
        for (int s = 0; s < 16; s++) {
            const int qo = 8 * s + 2 * tg;
            float2 A0 = *(const float2*)(qr0 + qo);   // (a0, a2) block0
            float2 A1 = *(const float2*)(qr1 + qo);   // (a1, a3) block0
            float2 B0 = *(const float2*)(qr2 + qo);   // block1
            float2 B1 = *(const float2*)(qr3 + qo);
#pragma unroll
            for (int nb = 0; nb < 8; nb++) {
                float2 kb2 = *(const float2*)(Ks + (8 * nb + g) * KP + qo);
                mma_tf32(sacc0[nb], A0.x, A1.x, A0.y, A1.y, kb2.x, kb2.y);
                mma_tf32(sacc1[nb], B0.x, B1.x, B0.y, B1.y, kb2.x, kb2.y);
            }
        }

        // ---- mask + exp, P -> smem (pair-permuted cols) ----
        const float* mt0 = mrow0 + kt * BK;
        const float* mt1 = mrow1 + kt * BK;
        const float* mt2 = mrow2 + kt * BK;
        const float* mt3 = mrow3 + kt * BK;
#pragma unroll
        for (int nb = 0; nb < 8; nb++) {
            const int mo = 8 * nb + 2 * tg;
            float2 m0 = *(const float2*)(mt0 + mo);
            float2 m1 = *(const float2*)(mt1 + mo);
            float2 m2 = *(const float2*)(mt2 + mo);
            float2 m3 = *(const float2*)(mt3 + mo);
            float p00 = __expf(sacc0[nb][0] + m0.x);
            float p01 = __expf(sacc0[nb][1] + m0.y);
            float p02 = __expf(sacc0[nb][2] + m1.x);
            float p03 = __expf(sacc0[nb][3] + m1.y);
            float p10 = __expf(sacc1[nb][0] + m2.x);
            float p11 = __expf(sacc1[nb][1] + m2.y);
            float p12 = __expf(sacc1[nb][2] + m3.x);
            float p13 = __expf(sacc1[nb][3] + m3.y);
            l00 += p00 + p01;  l01 += p02 + p03;
            l10 += p10 + p11;  l11 += p12 + p13;
            Ps[g        * PP + 8 * nb + pp0] = tf32r(p00);
            Ps[g        * PP + 8 * nb + pp1] = tf32r(p01);
            Ps[(g + 8)  * PP + 8 * nb + pp0] = tf32r(p02);
            Ps[(g + 8)  * PP + 8 * nb + pp1] = tf32r(p03);
            Ps[(g + 16) * PP + 8 * nb + pp0] = tf32r(p10);
            Ps[(g + 16) * PP + 8 * nb + pp1] = tf32r(p11);
            Ps[(g + 24) * PP + 8 * nb + pp0] = tf32r(p12);
            Ps[(g + 24) * PP + 8 * nb + pp1] = tf32r(p13);
        }
        __syncwarp();

        // ---- O += P V for both blocks, sharing V B-fragments ----
#pragma unroll
        for (int kb = 0; kb < 8; kb++) {
            const int po = 8 * kb + 2 * tg;
            float2 pa0 = *(const float2*)(Ps + g        * PP + po);   // (a0, a2)
            float2 pa1 = *(const float2*)(Ps + (g + 8)  * PP + po);   // (a1, a3)
            float2 pb0 = *(const float2*)(Ps + (g + 16) * PP + po);
            float2 pb1 = *(const float2*)(Ps + (g + 24) * PP + po);
#pragma unroll
            for (int db = 0; db < 16; db++) {
                float2 vb = *(const float2*)(Vs + (8 * db + g) * VP + po);
                mma_tf32(oacc0[db], pa0.x, pa1.x, pa0.y, pa1.y, vb.x, vb.y);
                mma_tf32(oacc1[db], pb0.x, pb1.x, pb0.y, pb1.y, vb.x, vb.y);
            }
        }
    }

    // ---- epilogue ----
    l00 += __shfl_xor_sync(0xffffffffu, l00, 1);
    l00 += __shfl_xor_sync(0xffffffffu, l00, 2);
    l01 += __shfl_xor_sync(0xffffffffu, l01, 1);
    l01 += __shfl_xor_sync(0xffffffffu, l01, 2);
    l10 += __shfl_xor_sync(0xffffffffu, l10, 1);
    l10 += __shfl_xor_sync(0xffffffffu, l10, 2);
    l11 += __shfl_xor_sync(0xffffffffu, l11, 1);
    l11 += __shfl_xor_sync(0xffffffffu, l11, 2);
    float i00 = 1.0f / l00, i01 = 1.0f / l01, i10 = 1.0f / l10, i11 = 1.0f / l11;

    float* op = out + base + (size_t)(q0 + w * 32) * DH;
#pragma unroll
    for (int db = 0; db < 16; db++) {
        int c = 8 * db + 2 * tg;
        *(float2*)(op + (size_t)g        * DH + c) = make_float2(oacc0[db][0] * i00, oacc0[db][1] * i00);
        *(float2*)(op + (size_t)(g + 8)  * DH + c) = make_float2(oacc0[db][2] * i01, oacc0[db][3] * i01);
        *(float2*)(op + (size_t)(g + 16) * DH + c) = make_float2(oacc1[db][0] * i10, oacc1[db][1] * i10);
        *(float2*)(op + (size_t)(g + 24) * DH + c) = make_float2(oacc1[db][2] * i11, oacc1[db][3] * i11);
    }
}

extern "C" void kernel_launch(void* const* d_in, const int* in_sizes, int n_in,
                              void* d_out, int out_size) {
    const float* q    = (const float*)d_in[0];
    const float* k    = (const float*)d_in[1];
    const float* v    = (const float*)d_in[2];
    const float* mask = (const float*)d_in[3];
    float* out = (float*)d_out;

    prep_qk<<<(size_t)NBH * SEQ * DH / 4 / 256, 256>>>(q, k);
    prep_v<<<dim3(SEQ / 32, DH / 32, NBH), dim3(32, 32)>>>(v);

    cudaFuncSetAttribute(fa_tf32_kernel,
                         cudaFuncAttributeMaxDynamicSharedMemorySize, SMEM_BYTES);
    cudaFuncSetAttribute(fa_tf32_kernel,
                         cudaFuncAttributePreferredSharedMemoryCarveout, 100);

    dim3 grid(SEQ / BQ, NBH);   // (8, 64)
    fa_tf32_kernel<<<grid, 256, SMEM_BYTES>>>(mask, out);
}

// round 11
// speedup vs baseline: 1.4916x; 1.4916x over previous
#include <cuda_runtime.h>
#include <cstdint>

#define SEQ   2048
#define DH    128
#define BQ    128
#define BK    64
#define NBH   64
#define NKT   (SEQ / BK)
#define KP    136            // K smem row stride (floats); 136 % 32 == 8 -> conflict-free LDS.64
#define VP    72             // V^T smem row stride; 72 % 32 == 8
#define PP    72             // P smem row stride; 72 % 32 == 8
#define KBUF  (64 * KP)      // 8704 floats
#define VBUF  (128 * VP)     // 9216 floats
#define KS_OFF 0
#define VS_OFF (2 * KBUF)                  // 17408
#define PS_OFF (VS_OFF + 2 * VBUF)         // 35840
#define SMEM_FLOATS (PS_OFF + 8 * 16 * PP) // 45056
#define SMEM_BYTES (SMEM_FLOATS * 4)       // 180224 B

__device__ float g_Qp[(size_t)NBH * SEQ * DH];   // tf32, pre-scaled, dim-pair-permuted
__device__ float g_Kp[(size_t)NBH * SEQ * DH];   // tf32, dim-pair-permuted
__device__ float g_Vt[(size_t)NBH * DH * SEQ];   // tf32, transposed [dim][key], key-pair-permuted

__device__ __forceinline__ float tf32r(float x) {
    uint32_t u; asm("cvt.rna.tf32.f32 %0, %1;" : "=r"(u) : "f"(x));
    return __uint_as_float(u);
}
__device__ __forceinline__ uint32_t smem_u32(const void* p) {
    uint32_t a;
    asm("{ .reg .u64 t; cvta.to.shared.u64 t, %1; cvt.u32.u64 %0, t; }" : "=r"(a) : "l"(p));
    return a;
}
__device__ __forceinline__ void cp16(uint32_t dst, const void* src) {
    asm volatile("cp.async.cg.shared.global [%0], [%1], 16;" :: "r"(dst), "l"(src) : "memory");
}
#define CP_COMMIT() asm volatile("cp.async.commit_group;" ::: "memory")
#define CP_WAIT1()  asm volatile("cp.async.wait_group 1;" ::: "memory")

__device__ __forceinline__ void mma_tf32(float c[4],
                                         float a0, float a1, float a2, float a3,
                                         float b0, float b1) {
    asm volatile(
        "mma.sync.aligned.m16n8k8.row.col.f32.tf32.tf32.f32 "
        "{%0,%1,%2,%3}, {%4,%5,%6,%7}, {%8,%9}, {%0,%1,%2,%3};"
        : "+f"(c[0]), "+f"(c[1]), "+f"(c[2]), "+f"(c[3])
        : "r"(__float_as_uint(a0)), "r"(__float_as_uint(a1)),
          "r"(__float_as_uint(a2)), "r"(__float_as_uint(a3)),
          "r"(__float_as_uint(b0)), "r"(__float_as_uint(b1)));
}

// Q/K prep: tf32 round (Q scaled); dims permuted within 8-groups: out=[i0,i4,i1,i5,i2,i6,i3,i7]
__global__ void prep_qk(const float* __restrict__ q, const float* __restrict__ k) {
    const float sc = 0.08838834764831845f;   // 1/sqrt(128)
    size_t i = (size_t)blockIdx.x * blockDim.x + threadIdx.x;   // one 8-float group
    const float4* q4 = (const float4*)q;
    const float4* k4 = (const float4*)k;
    float4 a0 = q4[2 * i], a1 = q4[2 * i + 1];
    float4 b0 = k4[2 * i], b1 = k4[2 * i + 1];
    a0.x = tf32r(a0.x * sc); a0.y = tf32r(a0.y * sc); a0.z = tf32r(a0.z * sc); a0.w = tf32r(a0.w * sc);
    a1.x = tf32r(a1.x * sc); a1.y = tf32r(a1.y * sc); a1.z = tf32r(a1.z * sc); a1.w = tf32r(a1.w * sc);
    b0.x = tf32r(b0.x); b0.y = tf32r(b0.y); b0.z = tf32r(b0.z); b0.w = tf32r(b0.w);
    b1.x = tf32r(b1.x); b1.y = tf32r(b1.y); b1.z = tf32r(b1.z); b1.w = tf32r(b1.w);
    ((float4*)g_Qp)[2 * i]     = make_float4(a0.x, a1.x, a0.y, a1.y);
    ((float4*)g_Qp)[2 * i + 1] = make_float4(a0.z, a1.z, a0.w, a1.w);
    ((float4*)g_Kp)[2 * i]     = make_float4(b0.x, b1.x, b0.y, b1.y);
    ((float4*)g_Kp)[2 * i + 1] = make_float4(b0.z, b1.z, b0.w, b1.w);
}

// V prep: tf32 round, transpose to [bh][dim][key], keys permuted within 8-groups
__global__ void prep_v(const float* __restrict__ v) {
    __shared__ float t[32][33];
    int k0 = blockIdx.x * 32, d0 = blockIdx.y * 32, bh = blockIdx.z;
    int tx = threadIdx.x, ty = threadIdx.y;
    t[ty][tx] = tf32r(v[(size_t)bh * SEQ * DH + (size_t)(k0 + ty) * DH + d0 + tx]);
    __syncthreads();
    int kperm = (tx & ~7) + ((tx & 3) * 2 + ((tx & 7) >> 2));
    g_Vt[(size_t)bh * DH * SEQ + (size_t)(d0 + ty) * SEQ + k0 + kperm] = t[tx][ty];
}

__device__ __forceinline__ void load_K(uint32_t sb, int tid, size_t base, int kt, int buf) {
    const float* kg = g_Kp + base + (size_t)kt * BK * DH;
#pragma unroll
    for (int it = 0; it < 8; it++) {
        int idx = tid + it * 256;        // 64 rows x 32 float4
        int n = idx >> 5, c = idx & 31;
        cp16(sb + (uint32_t)(KS_OFF + buf * KBUF + n * KP + 4 * c) * 4u,
             kg + (size_t)n * DH + 4 * c);
    }
}
__device__ __forceinline__ void load_V(uint32_t sb, int tid, int bh, int kt, int buf) {
    const float* vg = g_Vt + (size_t)bh * DH * SEQ + kt * BK;
#pragma unroll
    for (int it = 0; it < 8; it++) {
        int idx = tid + it * 256;        // 128 dim-rows x 16 float4
        int n = idx >> 4, c = idx & 15;
        cp16(sb + (uint32_t)(VS_OFF + buf * VBUF + n * VP + 4 * c) * 4u,
             vg + (size_t)n * SEQ + 4 * c);
    }
}

__global__ void __launch_bounds__(256, 1)
fa_tf32_kernel(const float* __restrict__ mask, float* __restrict__ out) {
    extern __shared__ float smem[];
    const uint32_t sb = smem_u32(smem);

    const int tid  = threadIdx.x;
    const int w    = tid >> 5;
    const int lane = tid & 31;
    const int g    = lane >> 2;
    const int tg   = lane & 3;

    float* Ps = smem + PS_OFF + w * (16 * PP);

    const int qt = blockIdx.x;
    const int bh = blockIdx.y;
    const int q0 = qt * BQ;
    const size_t base = (size_t)bh * SEQ * DH;

    // permuted store positions for sacc cols (2tg, 2tg+1)
    const int pp0 = ((2 * tg) & 3) * 2 + (tg >> 1);           // perm(2tg)
    const int pp1 = ((2 * tg + 1) & 3) * 2 + ((2 * tg + 1) >> 2);

    // ---- Q fragments from permuted gmem: float2 at 8s+2tg = (a0,a2); row g+8 = (a1,a3) ----
    const float* qp0 = g_Qp + base + (size_t)(q0 + w * 16 + g) * DH;
    const float* qp1 = qp0 + 8 * DH;
    float qa[16][4];
#pragma unroll
    for (int s = 0; s < 16; s++) {
        float2 p0 = *(const float2*)(qp0 + 8 * s + 2 * tg);
        float2 p1 = *(const float2*)(qp1 + 8 * s + 2 * tg);
        qa[s][0] = p0.x; qa[s][1] = p1.x; qa[s][2] = p0.y; qa[s][3] = p1.y;
    }

    float oacc[16][4];
#pragma unroll
    for (int d = 0; d < 16; d++) {
        oacc[d][0] = 0.f; oacc[d][1] = 0.f; oacc[d][2] = 0.f; oacc[d][3] = 0.f;
    }
    float lrow0 = 0.f, lrow1 = 0.f;

    const float* mk0 = mask + (size_t)(q0 + w * 16 + g)     * SEQ;
    const float* mk1 = mask + (size_t)(q0 + w * 16 + g + 8) * SEQ;

    load_K(sb, tid, base, 0, 0);
    load_V(sb, tid, bh, 0, 0);
    CP_COMMIT();

    for (int kt = 0; kt < NKT; kt++) {
        const int cur = kt & 1, nxt = cur ^ 1;
        __syncthreads();
        if (kt + 1 < NKT) { load_K(sb, tid, base, kt + 1, nxt); load_V(sb, tid, bh, kt + 1, nxt); }
        CP_COMMIT();
        CP_WAIT1();
        __syncthreads();

        const float* Ks = smem + KS_OFF + cur * KBUF;
        const float* Vs = smem + VS_OFF + cur * VBUF;

        // ---- hoist mask loads (fly under the QK MMAs) ----
        const float* mt0 = mk0 + kt * BK;
        const float* mt1 = mk1 + kt * BK;
        float2 mreg0[8], mreg1[8];
#pragma unroll
        for (int nb = 0; nb < 8; nb++) {
            mreg0[nb] = *(const float2*)(mt0 + 8 * nb + 2 * tg);
            mreg1[nb] = *(const float2*)(mt1 + 8 * nb + 2 * tg);
        }

        // ---- S = Q K^T (16x64 per warp), LDS.64 B-fragments ----
        float sacc[8][4];
#pragma unroll
        for (int nb = 0; nb < 8; nb++) {
            sacc[nb][0] = 0.f; sacc[nb][1] = 0.f; sacc[nb][2] = 0.f; sacc[nb][3] = 0.f;
        }
#pragma unroll
        for (int s = 0; s < 16; s++) {
#pragma unroll
            for (int nb = 0; nb < 8; nb++) {
                float2 kb2 = *(const float2*)(Ks + (8 * nb + g) * KP + 8 * s + 2 * tg);
                mma_tf32(sacc[nb], qa[s][0], qa[s][1], qa[s][2], qa[s][3], kb2.x, kb2.y);
            }
        }

        // ---- mask + exp, P -> smem at permuted cols ----
#pragma unroll
        for (int nb = 0; nb < 8; nb++) {
            float p0 = __expf(sacc[nb][0] + mreg0[nb].x);
            float p1 = __expf(sacc[nb][1] + mreg0[nb].y);
            float p2 = __expf(sacc[nb][2] + mreg1[nb].x);
            float p3 = __expf(sacc[nb][3] + mreg1[nb].y);
            lrow0 += p0 + p1;
            lrow1 += p2 + p3;
            Ps[g       * PP + 8 * nb + pp0] = tf32r(p0);
            Ps[g       * PP + 8 * nb + pp1] = tf32r(p1);
            Ps[(g + 8) * PP + 8 * nb + pp0] = tf32r(p2);
            Ps[(g + 8) * PP + 8 * nb + pp1] = tf32r(p3);
        }
        __syncwarp();

        // ---- O += P V, LDS.64 A- and B-fragments ----
#pragma unroll
        for (int kb = 0; kb < 8; kb++) {
            float2 pa0 = *(const float2*)(Ps + g       * PP + 8 * kb + 2 * tg);  // (a0, a2)
            float2 pa1 = *(const float2*)(Ps + (g + 8) * PP + 8 * kb + 2 * tg);  // (a1, a3)
#pragma unroll
            for (int db = 0; db < 16; db++) {
                float2 vb = *(const float2*)(Vs + (8 * db + g) * VP + 8 * kb + 2 * tg);
                mma_tf32(oacc[db], pa0.x, pa1.x, pa0.y, pa1.y, vb.x, vb.y);
            }
        }
    }

    // ---- epilogue ----
    lrow0 += __shfl_xor_sync(0xffffffffu, lrow0, 1);
    lrow0 += __shfl_xor_sync(0xffffffffu, lrow0, 2);
    lrow1 += __shfl_xor_sync(0xffffffffu, lrow1, 1);
    lrow1 += __shfl_xor_sync(0xffffffffu, lrow1, 2);
    float inv0 = 1.0f / lrow0;
    float inv1 = 1.0f / lrow1;
    float* op = out + base + (size_t)(q0 + w * 16) * DH;
#pragma unroll
    for (int db = 0; db < 16; db++) {
        int c = 8 * db + 2 * tg;
        *(float2*)(op + (size_t)g       * DH + c) = make_float2(oacc[db][0] * inv0, oacc[db][1] * inv0);
        *(float2*)(op + (size_t)(g + 8) * DH + c) = make_float2(oacc[db][2] * inv1, oacc[db][3] * inv1);
    }
}

extern "C" void kernel_launch(void* const* d_in, const int* in_sizes, int n_in,
                              void* d_out, int out_size) {
    const float* q    = (const float*)d_in[0];
    const float* k    = (const float*)d_in[1];
    const float* v    = (const float*)d_in[2];
    const float* mask = (const float*)d_in[3];
    float* out = (float*)d_out;

    prep_qk<<<(size_t)NBH * SEQ * DH / 8 / 256, 256>>>(q, k);
    prep_v<<<dim3(SEQ / 32, DH / 32, NBH), dim3(32, 32)>>>(v);

    cudaFuncSetAttribute(fa_tf32_kernel,
                         cudaFuncAttributeMaxDynamicSharedMemorySize, SMEM_BYTES);
    cudaFuncSetAttribute(fa_tf32_kernel,
                         cudaFuncAttributePreferredSharedMemoryCarveout, 100);

    dim3 grid(SEQ / BQ, NBH);   // (16, 64)
    fa_tf32_kernel<<<grid, 256, SMEM_BYTES>>>(mask, out);
}

// round 12
// speedup vs baseline: 1.5413x; 1.0334x over previous
#include <cuda_runtime.h>
#include <cstdint>

#define SEQ   2048
#define DH    128
#define BQ    128
#define BK    64
#define NBH   64
#define NKT   (SEQ / BK)
#define KP    136            // K smem row stride (floats); %32==8 -> conflict-free LDS.64
#define VP    72
#define PP    72
#define KBUF  (64 * KP)
#define VBUF  (128 * VP)
#define KS_OFF 0
#define VS_OFF (2 * KBUF)
#define PS_OFF (VS_OFF + 2 * VBUF)
#define SMEM_FLOATS (PS_OFF + 8 * 16 * PP)
#define SMEM_BYTES (SMEM_FLOATS * 4)       // 180224 B

__device__ float g_Qp[(size_t)NBH * SEQ * DH];   // tf32, pre-scaled, dim-pair-permuted
__device__ float g_Kp[(size_t)NBH * SEQ * DH];   // tf32, dim-pair-permuted
__device__ float g_Vt[(size_t)NBH * DH * SEQ];   // tf32, [dim][key], key-pair-permuted

__device__ __forceinline__ float tf32r(float x) {
    uint32_t u; asm("cvt.rna.tf32.f32 %0, %1;" : "=r"(u) : "f"(x));
    return __uint_as_float(u);
}
__device__ __forceinline__ uint32_t smem_u32(const void* p) {
    uint32_t a;
    asm("{ .reg .u64 t; cvta.to.shared.u64 t, %1; cvt.u32.u64 %0, t; }" : "=r"(a) : "l"(p));
    return a;
}
__device__ __forceinline__ void cp16(uint32_t dst, const void* src) {
    asm volatile("cp.async.cg.shared.global [%0], [%1], 16;" :: "r"(dst), "l"(src) : "memory");
}
#define CP_COMMIT() asm volatile("cp.async.commit_group;" ::: "memory")
#define CP_WAIT1()  asm volatile("cp.async.wait_group 1;" ::: "memory")

__device__ __forceinline__ void mma_tf32(float c[4],
                                         float a0, float a1, float a2, float a3,
                                         float b0, float b1) {
    asm volatile(
        "mma.sync.aligned.m16n8k8.row.col.f32.tf32.tf32.f32 "
        "{%0,%1,%2,%3}, {%4,%5,%6,%7}, {%8,%9}, {%0,%1,%2,%3};"
        : "+f"(c[0]), "+f"(c[1]), "+f"(c[2]), "+f"(c[3])
        : "r"(__float_as_uint(a0)), "r"(__float_as_uint(a1)),
          "r"(__float_as_uint(a2)), "r"(__float_as_uint(a3)),
          "r"(__float_as_uint(b0)), "r"(__float_as_uint(b1)));
}

// fused prep: one 32x32 tile per block; q/k rounded+dim-permuted, v rounded+transposed+key-permuted
__global__ void prep_fused(const float* __restrict__ q, const float* __restrict__ k,
                           const float* __restrict__ v) {
    __shared__ float t[32][33];
    const float sc = 0.08838834764831845f;   // 1/sqrt(128)
    int k0 = blockIdx.x * 32, d0 = blockIdx.y * 32, bh = blockIdx.z;
    int tx = threadIdx.x, ty = threadIdx.y;
    size_t base = (size_t)bh * SEQ * DH;
    size_t src = base + (size_t)(k0 + ty) * DH + d0 + tx;

    // dim-permute position for column d0+tx (permute within 8-groups)
    int c = d0 + tx;
    int cperm = (c & ~7) + ((c & 3) * 2 + ((c & 7) >> 2));
    size_t dstqk = base + (size_t)(k0 + ty) * DH + cperm;
    g_Qp[dstqk] = tf32r(q[src] * sc);
    g_Kp[dstqk] = tf32r(k[src]);

    // v: stage, transpose, key-permute
    t[ty][tx] = tf32r(v[src]);
    __syncthreads();
    int kperm = (tx & ~7) + ((tx & 3) * 2 + ((tx & 7) >> 2));
    g_Vt[(size_t)bh * DH * SEQ + (size_t)(d0 + ty) * SEQ + k0 + kperm] = t[tx][ty];
}

__device__ __forceinline__ void load_K(uint32_t sb, int tid, size_t base, int kt, int buf) {
    const float* kg = g_Kp + base + (size_t)kt * BK * DH;
#pragma unroll
    for (int it = 0; it < 8; it++) {
        int idx = tid + it * 256;
        int n = idx >> 5, c = idx & 31;
        cp16(sb + (uint32_t)(KS_OFF + buf * KBUF + n * KP + 4 * c) * 4u,
             kg + (size_t)n * DH + 4 * c);
    }
}
__device__ __forceinline__ void load_V(uint32_t sb, int tid, int bh, int kt, int buf) {
    const float* vg = g_Vt + (size_t)bh * DH * SEQ + kt * BK;
#pragma unroll
    for (int it = 0; it < 8; it++) {
        int idx = tid + it * 256;
        int n = idx >> 4, c = idx & 15;
        cp16(sb + (uint32_t)(VS_OFF + buf * VBUF + n * VP + 4 * c) * 4u,
             vg + (size_t)n * SEQ + 4 * c);
    }
}

__global__ void __launch_bounds__(256, 1)
fa_tf32_kernel(const float* __restrict__ mask, float* __restrict__ out) {
    extern __shared__ float smem[];
    const uint32_t sb = smem_u32(smem);

    const int tid  = threadIdx.x;
    const int w    = tid >> 5;
    const int lane = tid & 31;
    const int g    = lane >> 2;
    const int tg   = lane & 3;

    float* Ps = smem + PS_OFF + w * (16 * PP);

    const int qt = blockIdx.x;
    const int bh = blockIdx.y;
    const int q0 = qt * BQ;
    const size_t base = (size_t)bh * SEQ * DH;

    // permuted store positions for sacc cols (2tg, 2tg+1)
    const int pp0 = ((2 * tg) & 3) * 2 + ((2 * tg) >> 2);
    const int pp1 = ((2 * tg + 1) & 3) * 2 + ((2 * tg + 1) >> 2);

    // Q fragments from permuted gmem
    const float* qp0 = g_Qp + base + (size_t)(q0 + w * 16 + g) * DH;
    const float* qp1 = qp0 + 8 * DH;
    float qa[16][4];
#pragma unroll
    for (int s = 0; s < 16; s++) {
        float2 p0 = *(const float2*)(qp0 + 8 * s + 2 * tg);
        float2 p1 = *(const float2*)(qp1 + 8 * s + 2 * tg);
        qa[s][0] = p0.x; qa[s][1] = p1.x; qa[s][2] = p0.y; qa[s][3] = p1.y;
    }

    float oacc[16][4];
#pragma unroll
    for (int d = 0; d < 16; d++) {
        oacc[d][0] = 0.f; oacc[d][1] = 0.f; oacc[d][2] = 0.f; oacc[d][3] = 0.f;
    }
    float lrow0 = 0.f, lrow1 = 0.f;

    const float* mk0 = mask + (size_t)(q0 + w * 16 + g)     * SEQ;
    const float* mk1 = mask + (size_t)(q0 + w * 16 + g + 8) * SEQ;

    load_K(sb, tid, base, 0, 0);
    load_V(sb, tid, bh, 0, 0);
    CP_COMMIT();

    for (int kt = 0; kt < NKT; kt++) {
        const int cur = kt & 1, nxt = cur ^ 1;
        __syncthreads();
        if (kt + 1 < NKT) { load_K(sb, tid, base, kt + 1, nxt); load_V(sb, tid, bh, kt + 1, nxt); }
        CP_COMMIT();
        CP_WAIT1();
        __syncthreads();

        const float* Ks = smem + KS_OFF + cur * KBUF;
        const float* Vs = smem + VS_OFF + cur * VBUF;

        // hoist mask loads (fly under the MMAs)
        const float* mt0 = mk0 + kt * BK;
        const float* mt1 = mk1 + kt * BK;
        float2 mreg0[8], mreg1[8];
#pragma unroll
        for (int nb = 0; nb < 8; nb++) {
            mreg0[nb] = *(const float2*)(mt0 + 8 * nb + 2 * tg);
            mreg1[nb] = *(const float2*)(mt1 + 8 * nb + 2 * tg);
        }

        float sacc[8][4];
#pragma unroll
        for (int nb = 0; nb < 8; nb++) {
            sacc[nb][0] = 0.f; sacc[nb][1] = 0.f; sacc[nb][2] = 0.f; sacc[nb][3] = 0.f;
        }

        // ---- QK half 0 (nb 0..3) ----
#pragma unroll
        for (int s = 0; s < 16; s++) {
#pragma unroll
            for (int nb = 0; nb < 4; nb++) {
                float2 kb2 = *(const float2*)(Ks + (8 * nb + g) * KP + 8 * s + 2 * tg);
                mma_tf32(sacc[nb], qa[s][0], qa[s][1], qa[s][2], qa[s][3], kb2.x, kb2.y);
            }
        }
        // ---- exp half 0 interleaves with QK half 1 MMAs (independent) ----
#pragma unroll
        for (int nb = 0; nb < 4; nb++) {
            float p0 = __expf(sacc[nb][0] + mreg0[nb].x);
            float p1 = __expf(sacc[nb][1] + mreg0[nb].y);
            float p2 = __expf(sacc[nb][2] + mreg1[nb].x);
            float p3 = __expf(sacc[nb][3] + mreg1[nb].y);
            lrow0 += p0 + p1;
            lrow1 += p2 + p3;
            Ps[g       * PP + 8 * nb + pp0] = tf32r(p0);
            Ps[g       * PP + 8 * nb + pp1] = tf32r(p1);
            Ps[(g + 8) * PP + 8 * nb + pp0] = tf32r(p2);
            Ps[(g + 8) * PP + 8 * nb + pp1] = tf32r(p3);
        }
        // ---- QK half 1 (nb 4..7) ----
#pragma unroll
        for (int s = 0; s < 16; s++) {
#pragma unroll
            for (int nb = 4; nb < 8; nb++) {
                float2 kb2 = *(const float2*)(Ks + (8 * nb + g) * KP + 8 * s + 2 * tg);
                mma_tf32(sacc[nb], qa[s][0], qa[s][1], qa[s][2], qa[s][3], kb2.x, kb2.y);
            }
        }
        // ---- exp half 1 ----
#pragma unroll
        for (int nb = 4; nb < 8; nb++) {
            float p0 = __expf(sacc[nb][0] + mreg0[nb].x);
            float p1 = __expf(sacc[nb][1] + mreg0[nb].y);
            float p2 = __expf(sacc[nb][2] + mreg1[nb].x);
            float p3 = __expf(sacc[nb][3] + mreg1[nb].y);
            lrow0 += p0 + p1;
            lrow1 += p2 + p3;
            Ps[g       * PP + 8 * nb + pp0] = tf32r(p0);
            Ps[g       * PP + 8 * nb + pp1] = tf32r(p1);
            Ps[(g + 8) * PP + 8 * nb + pp0] = tf32r(p2);
            Ps[(g + 8) * PP + 8 * nb + pp1] = tf32r(p3);
        }
        __syncwarp();

        // ---- O += P V ----
#pragma unroll
        for (int kb = 0; kb < 8; kb++) {
            float2 pa0 = *(const float2*)(Ps + g       * PP + 8 * kb + 2 * tg);
            float2 pa1 = *(const float2*)(Ps + (g + 8) * PP + 8 * kb + 2 * tg);
#pragma unroll
            for (int db = 0; db < 16; db++) {
                float2 vb = *(const float2*)(Vs + (8 * db + g) * VP + 8 * kb + 2 * tg);
                mma_tf32(oacc[db], pa0.x, pa1.x, pa0.y, pa1.y, vb.x, vb.y);
            }
        }
    }

    // ---- epilogue ----
    lrow0 += __shfl_xor_sync(0xffffffffu, lrow0, 1);
    lrow0 += __shfl_xor_sync(0xffffffffu, lrow0, 2);
    lrow1 += __shfl_xor_sync(0xffffffffu, lrow1, 1);
    lrow1 += __shfl_xor_sync(0xffffffffu, lrow1, 2);
    float inv0 = 1.0f / lrow0;
    float inv1 = 1.0f / lrow1;
    float* op = out + base + (size_t)(q0 + w * 16) * DH;
#pragma unroll
    for (int db = 0; db < 16; db++) {
        int c = 8 * db + 2 * tg;
        *(float2*)(op + (size_t)g       * DH + c) = make_float2(oacc[db][0] * inv0, oacc[db][1] * inv0);
        *(float2*)(op + (size_t)(g + 8) * DH + c) = make_float2(oacc[db][2] * inv1, oacc[db][3] * inv1);
    }
}

extern "C" void kernel_launch(void* const* d_in, const int* in_sizes, int n_in,
                              void* d_out, int out_size) {
    const float* q    = (const float*)d_in[0];
    const float* k    = (const float*)d_in[1];
    const float* v    = (const float*)d_in[2];
    const float* mask = (const float*)d_in[3];
    float* out = (float*)d_out;

    prep_fused<<<dim3(SEQ / 32, DH / 32, NBH), dim3(32, 32)>>>(q, k, v);

    cudaFuncSetAttribute(fa_tf32_kernel,
                         cudaFuncAttributeMaxDynamicSharedMemorySize, SMEM_BYTES);
    cudaFuncSetAttribute(fa_tf32_kernel,
                         cudaFuncAttributePreferredSharedMemoryCarveout, 100);

    dim3 grid(SEQ / BQ, NBH);   // (16, 64)
    fa_tf32_kernel<<<grid, 256, SMEM_BYTES>>>(mask, out);
}